// round 1
// baseline (speedup 1.0000x reference)
#include <cuda_runtime.h>
#include <math.h>

#define NPTS 8192
#define PD   16
#define IND  256
#define OUTD 128
#define HH0  512
#define HH1  1024
#define HH2  1024
#define HH3  512
#define NP   (NPTS*PD)   // 131072

// Scratch activations (device globals: allocation-free per harness rules)
__device__ float g_h0[(size_t)NP * HH0];
__device__ float g_h1[(size_t)NP * HH1];
__device__ float g_h2[(size_t)NP * HH2];
__device__ float g_h3[(size_t)NP * HH3];

__device__ __forceinline__ float softplusf(float x) {
    // stable: max(x,0) + log1p(exp(-|x|))
    return fmaxf(x, 0.0f) + log1pf(expf(-fabsf(x)));
}

// ---------------------------------------------------------------------------
// Generic 128x128 tiled SGEMM: C[m,n] = sum_k A[m,k] * W[n,k] + B[n]
// A row-major with stride lda (rows indexed by m), W row-major K-contiguous,
// per-blockIdx.z offsets Az/Wz/Bz/Cz allow batched (per-p) weights.
// EPI: 0 = linear, 1 = relu
// ---------------------------------------------------------------------------
template<int EPI>
__global__ __launch_bounds__(256)
void sgemm_k(const float* __restrict__ A, long lda, long Az,
             const float* __restrict__ W, long Wz,
             const float* __restrict__ B, long Bz,
             float* __restrict__ C, long ldc, long Cz,
             int K)
{
    __shared__ float As[16][128];
    __shared__ float Bs[16][128];
    const int tid = threadIdx.x;
    const long m0 = (long)blockIdx.x * 128;
    const long n0 = (long)blockIdx.y * 128;
    const int  z  = blockIdx.z;

    A += (long)z * Az;
    W += (long)z * Wz + n0 * (long)K;
    B += (long)z * Bz + n0;
    C += (long)z * Cz;

    const int trow = tid >> 4;        // 0..15 (M direction, 8 rows each)
    const int tcol = tid & 15;        // 0..15 (N direction, 8 cols each)
    const int lrow = tid >> 2;        // 0..63 (tile load row)
    const int lcol = (tid & 3) << 2;  // 0,4,8,12 (tile load col, float4)

    float acc[8][8] = {};

    const float* Ap = A + (m0 + lrow) * lda + lcol;
    const float* Wp = W + (long)lrow * K + lcol;

    for (int k0 = 0; k0 < K; k0 += 16) {
        #pragma unroll
        for (int i = 0; i < 2; i++) {
            float4 va = *(const float4*)(Ap + (long)(i * 64) * lda + k0);
            float4 vb = *(const float4*)(Wp + (long)(i * 64) * K + k0);
            As[lcol + 0][lrow + i * 64] = va.x;
            As[lcol + 1][lrow + i * 64] = va.y;
            As[lcol + 2][lrow + i * 64] = va.z;
            As[lcol + 3][lrow + i * 64] = va.w;
            Bs[lcol + 0][lrow + i * 64] = vb.x;
            Bs[lcol + 1][lrow + i * 64] = vb.y;
            Bs[lcol + 2][lrow + i * 64] = vb.z;
            Bs[lcol + 3][lrow + i * 64] = vb.w;
        }
        __syncthreads();
        #pragma unroll
        for (int k = 0; k < 16; k++) {
            float4 a0 = *(const float4*)&As[k][trow * 8];
            float4 a1 = *(const float4*)&As[k][trow * 8 + 4];
            float4 b0 = *(const float4*)&Bs[k][tcol * 8];
            float4 b1 = *(const float4*)&Bs[k][tcol * 8 + 4];
            float ra[8] = {a0.x, a0.y, a0.z, a0.w, a1.x, a1.y, a1.z, a1.w};
            float rb[8] = {b0.x, b0.y, b0.z, b0.w, b1.x, b1.y, b1.z, b1.w};
            #pragma unroll
            for (int i = 0; i < 8; i++)
                #pragma unroll
                for (int j = 0; j < 8; j++)
                    acc[i][j] = fmaf(ra[i], rb[j], acc[i][j]);
        }
        __syncthreads();
    }

    #pragma unroll
    for (int i = 0; i < 8; i++) {
        long m = m0 + trow * 8 + i;
        float* Crow = C + m * ldc + n0;
        #pragma unroll
        for (int jj = 0; jj < 2; jj++) {
            int n = tcol * 8 + jj * 4;
            float4 v;
            v.x = acc[i][jj * 4 + 0] + B[n + 0];
            v.y = acc[i][jj * 4 + 1] + B[n + 1];
            v.z = acc[i][jj * 4 + 2] + B[n + 2];
            v.w = acc[i][jj * 4 + 3] + B[n + 3];
            if (EPI == 1) {
                v.x = fmaxf(v.x, 0.0f);
                v.y = fmaxf(v.y, 0.0f);
                v.z = fmaxf(v.z, 0.0f);
                v.w = fmaxf(v.w, 0.0f);
            }
            *(float4*)(Crow + n) = v;
        }
    }
}

// ---------------------------------------------------------------------------
// Final layer: out[n,p,:] = h3[n,p,:] @ W_out[p]^T + b_out[p]
// blockIdx.y: 0 -> mu half (cols 0..127), 1 -> var half (cols 128..255)
// var = 0.01 + 0.99 * softplus(v); mask -> NaN
// Output layout: mu (N*P*128 floats) followed by var (N*P*128 floats)
// ---------------------------------------------------------------------------
__global__ __launch_bounds__(256)
void final_k(const float* __restrict__ h3,
             const float* __restrict__ Wout,
             const float* __restrict__ bout,
             const unsigned char* __restrict__ mask,
             float* __restrict__ out)
{
    __shared__ float As[16][128];
    __shared__ float Bs[16][128];
    const int tid  = threadIdx.x;
    const long m0  = (long)blockIdx.x * 128;
    const int half = blockIdx.y;        // 0 = mu, 1 = var
    const int p    = blockIdx.z;
    const long n0  = (long)half * 128;

    const float* A   = h3 + (long)p * HH3;
    const long   lda = (long)PD * HH3;
    const float* W   = Wout + ((long)p * (2 * OUTD) + n0) * HH3;
    const float* B   = bout + (long)p * (2 * OUTD) + n0;

    const int trow = tid >> 4;
    const int tcol = tid & 15;
    const int lrow = tid >> 2;
    const int lcol = (tid & 3) << 2;

    float acc[8][8] = {};

    const float* Ap = A + (m0 + lrow) * lda + lcol;
    const float* Wp = W + (long)lrow * HH3 + lcol;

    for (int k0 = 0; k0 < HH3; k0 += 16) {
        #pragma unroll
        for (int i = 0; i < 2; i++) {
            float4 va = *(const float4*)(Ap + (long)(i * 64) * lda + k0);
            float4 vb = *(const float4*)(Wp + (long)(i * 64) * HH3 + k0);
            As[lcol + 0][lrow + i * 64] = va.x;
            As[lcol + 1][lrow + i * 64] = va.y;
            As[lcol + 2][lrow + i * 64] = va.z;
            As[lcol + 3][lrow + i * 64] = va.w;
            Bs[lcol + 0][lrow + i * 64] = vb.x;
            Bs[lcol + 1][lrow + i * 64] = vb.y;
            Bs[lcol + 2][lrow + i * 64] = vb.z;
            Bs[lcol + 3][lrow + i * 64] = vb.w;
        }
        __syncthreads();
        #pragma unroll
        for (int k = 0; k < 16; k++) {
            float4 a0 = *(const float4*)&As[k][trow * 8];
            float4 a1 = *(const float4*)&As[k][trow * 8 + 4];
            float4 b0 = *(const float4*)&Bs[k][tcol * 8];
            float4 b1 = *(const float4*)&Bs[k][tcol * 8 + 4];
            float ra[8] = {a0.x, a0.y, a0.z, a0.w, a1.x, a1.y, a1.z, a1.w};
            float rb[8] = {b0.x, b0.y, b0.z, b0.w, b1.x, b1.y, b1.z, b1.w};
            #pragma unroll
            for (int i = 0; i < 8; i++)
                #pragma unroll
                for (int j = 0; j < 8; j++)
                    acc[i][j] = fmaf(ra[i], rb[j], acc[i][j]);
        }
        __syncthreads();
    }

    const float nanv = __int_as_float(0x7FC00000);
    float* outbase = out + (long)half * ((long)NP * OUTD);

    #pragma unroll
    for (int i = 0; i < 8; i++) {
        long npt = m0 + trow * 8 + i;       // n index in [0, NPTS)
        long row = npt * PD + p;            // flattened (n,p)
        bool msk = (mask[row] != 0);
        float* orow = outbase + row * OUTD;
        #pragma unroll
        for (int jj = 0; jj < 2; jj++) {
            int n = tcol * 8 + jj * 4;
            float4 v;
            v.x = acc[i][jj * 4 + 0] + B[n + 0];
            v.y = acc[i][jj * 4 + 1] + B[n + 1];
            v.z = acc[i][jj * 4 + 2] + B[n + 2];
            v.w = acc[i][jj * 4 + 3] + B[n + 3];
            if (half == 1) {
                v.x = 0.01f + 0.99f * softplusf(v.x);
                v.y = 0.01f + 0.99f * softplusf(v.y);
                v.z = 0.01f + 0.99f * softplusf(v.z);
                v.w = 0.01f + 0.99f * softplusf(v.w);
            }
            if (msk) { v.x = nanv; v.y = nanv; v.z = nanv; v.w = nanv; }
            *(float4*)(orow + n) = v;
        }
    }
}

extern "C" void kernel_launch(void* const* d_in, const int* in_sizes, int n_in,
                              void* d_out, int out_size)
{
    const float* x    = (const float*)d_in[0];
    const unsigned char* mask = (const unsigned char*)d_in[1];
    const float* W_in = (const float*)d_in[2];
    const float* b_in = (const float*)d_in[3];
    const float* W1   = (const float*)d_in[4];
    const float* b1   = (const float*)d_in[5];
    const float* W2   = (const float*)d_in[6];
    const float* b2   = (const float*)d_in[7];
    const float* W3   = (const float*)d_in[8];
    const float* b3   = (const float*)d_in[9];
    const float* Wout = (const float*)d_in[10];
    const float* bout = (const float*)d_in[11];
    float* out = (float*)d_out;

    float *h0, *h1, *h2, *h3;
    cudaGetSymbolAddress((void**)&h0, g_h0);
    cudaGetSymbolAddress((void**)&h1, g_h1);
    cudaGetSymbolAddress((void**)&h2, g_h2);
    cudaGetSymbolAddress((void**)&h3, g_h3);

    // Layer 0: per-p input projection (linear). x: (N,P,256), W_in: (P,512,256)
    sgemm_k<0><<<dim3(NPTS / 128, HH0 / 128, PD), 256>>>(
        x, (long)PD * IND, (long)IND,
        W_in, (long)HH0 * IND,
        b_in, (long)HH0,
        h0, (long)PD * HH0, (long)HH0, IND);

    // Layer 1: relu(h0 @ W1^T + b1), M = N*P
    sgemm_k<1><<<dim3(NP / 128, HH1 / 128, 1), 256>>>(
        h0, HH0, 0, W1, 0, b1, 0, h1, HH1, 0, HH0);

    // Layer 2
    sgemm_k<1><<<dim3(NP / 128, HH2 / 128, 1), 256>>>(
        h1, HH1, 0, W2, 0, b2, 0, h2, HH2, 0, HH1);

    // Layer 3
    sgemm_k<1><<<dim3(NP / 128, HH3 / 128, 1), 256>>>(
        h2, HH2, 0, W3, 0, b3, 0, h3, HH3, 0, HH2);

    // Output head: per-p, mu + var(softplus) + mask
    final_k<<<dim3(NPTS / 128, 2, PD), 256>>>(h3, Wout, bout, mask, out);
}

// round 3
// speedup vs baseline: 2.7311x; 2.7311x over previous
#include <cuda_runtime.h>
#include <cuda_fp16.h>
#include <cstdint>
#include <math.h>

#define NPTS 8192
#define PD   16
#define IND  256
#define OUTD 128
#define HH0  512
#define HH1  1024
#define HH2  1024
#define HH3  512
#define NP   (NPTS*PD)   // 131072

// ---------------------------------------------------------------------------
// Device-global scratch (allocation-free per harness rules)
// Activations and inputs/weights stored as hi/lo half pairs (fp16x2 split).
// ---------------------------------------------------------------------------
__device__ __half g_xh[(size_t)NP * IND];
__device__ __half g_xl[(size_t)NP * IND];
__device__ __half g_h0h[(size_t)NP * HH0];
__device__ __half g_h0l[(size_t)NP * HH0];
__device__ __half g_h1h[(size_t)NP * HH1];
__device__ __half g_h1l[(size_t)NP * HH1];
__device__ __half g_h2h[(size_t)NP * HH2];
__device__ __half g_h2l[(size_t)NP * HH2];
__device__ __half g_h3h[(size_t)NP * HH3];
__device__ __half g_h3l[(size_t)NP * HH3];
__device__ __half g_wih[(size_t)PD * HH0 * IND];
__device__ __half g_wil[(size_t)PD * HH0 * IND];
__device__ __half g_w1h[(size_t)HH1 * HH0];
__device__ __half g_w1l[(size_t)HH1 * HH0];
__device__ __half g_w2h[(size_t)HH2 * HH1];
__device__ __half g_w2l[(size_t)HH2 * HH1];
__device__ __half g_w3h[(size_t)HH3 * HH2];
__device__ __half g_w3l[(size_t)HH3 * HH2];
__device__ __half g_woh[(size_t)PD * 2 * OUTD * HH3];
__device__ __half g_wol[(size_t)PD * 2 * OUTD * HH3];

// ---------------------------------------------------------------------------
// Helpers
// ---------------------------------------------------------------------------
__device__ __forceinline__ uint32_t smem_u32(const void* p) {
    uint32_t a;
    asm("{ .reg .u64 t; cvta.to.shared.u64 t, %1; cvt.u32.u64 %0, t; }" : "=r"(a) : "l"(p));
    return a;
}
__device__ __forceinline__ void cp16(uint32_t dst, const void* src) {
    asm volatile("cp.async.cg.shared.global [%0], [%1], 16;" :: "r"(dst), "l"(src));
}
__device__ __forceinline__ void cp_commit() {
    asm volatile("cp.async.commit_group;" ::: "memory");
}
__device__ __forceinline__ void cp_wait1() {
    asm volatile("cp.async.wait_group 1;" ::: "memory");
}
__device__ __forceinline__ void cp_wait0() {
    asm volatile("cp.async.wait_group 0;" ::: "memory");
}
__device__ __forceinline__ void ldsm4(uint32_t* r, uint32_t addr) {
    asm volatile("ldmatrix.sync.aligned.m8n8.x4.shared.b16 {%0,%1,%2,%3}, [%4];"
                 : "=r"(r[0]), "=r"(r[1]), "=r"(r[2]), "=r"(r[3]) : "r"(addr));
}
__device__ __forceinline__ void mma16816(float* d, const uint32_t* a, const uint32_t* b) {
    asm volatile("mma.sync.aligned.m16n8k16.row.col.f32.f16.f16.f32 "
                 "{%0,%1,%2,%3}, {%4,%5,%6,%7}, {%8,%9}, {%0,%1,%2,%3};"
                 : "+f"(d[0]), "+f"(d[1]), "+f"(d[2]), "+f"(d[3])
                 : "r"(a[0]), "r"(a[1]), "r"(a[2]), "r"(a[3]), "r"(b[0]), "r"(b[1]));
}
__device__ __forceinline__ float softplusf(float x) {
    return fmaxf(x, 0.0f) + log1pf(expf(-fabsf(x)));
}

// ---------------------------------------------------------------------------
// fp32 -> (hi, lo) fp16 split converter (grid-stride, float4)
// ---------------------------------------------------------------------------
__global__ void cvt_hilo(const float* __restrict__ s, __half* __restrict__ hi,
                         __half* __restrict__ lo, long n4)
{
    long i = blockIdx.x * (long)blockDim.x + threadIdx.x;
    const long stride = (long)gridDim.x * blockDim.x;
    for (; i < n4; i += stride) {
        float4 v = ((const float4*)s)[i];
        __half h0 = __float2half_rn(v.x), h1 = __float2half_rn(v.y);
        __half h2 = __float2half_rn(v.z), h3 = __float2half_rn(v.w);
        __half l0 = __float2half_rn(v.x - __half2float(h0));
        __half l1 = __float2half_rn(v.y - __half2float(h1));
        __half l2 = __float2half_rn(v.z - __half2float(h2));
        __half l3 = __float2half_rn(v.w - __half2float(h3));
        ((__half2*)hi)[2 * i]     = __halves2half2(h0, h1);
        ((__half2*)hi)[2 * i + 1] = __halves2half2(h2, h3);
        ((__half2*)lo)[2 * i]     = __halves2half2(l0, l1);
        ((__half2*)lo)[2 * i + 1] = __halves2half2(l2, l3);
    }
}

// ---------------------------------------------------------------------------
// fp16x2-split tensor-core GEMM: C[m,n] = sum_k A[m,k]*W[n,k] + bias[n]
// Tile 128(M)x128(N), K-chunk 32, 2-stage cp.async pipeline, 8 warps (4Mx2N),
// warp tile 32x64. Smem rows padded to 40 halves (80B) => ldmatrix conflict-free.
// EPI: 0 linear (write hi/lo halves), 1 relu (hi/lo), 2 final head (fp32 out,
//      softplus on var half, mask -> NaN)
// ---------------------------------------------------------------------------
#define ROWB  80                   // padded row pitch in bytes (40 halves)
#define TA_H  0
#define TA_L  10240
#define TB_H  20480
#define TB_L  30720
#define STG   40960
#define SBIAS (2*STG)              // 128 floats
#define SMEMT (2*STG + 512)

template<int EPI>
__global__ void __launch_bounds__(256, 2)
hgemm(const __half* __restrict__ Ah, const __half* __restrict__ Al, long lda, long Az,
      const __half* __restrict__ Wh, const __half* __restrict__ Wl, long Wz,
      const float* __restrict__ Bv, long Bz,
      __half* __restrict__ Ch, __half* __restrict__ Cl, long ldc, long Cz,
      float* __restrict__ Fout, const unsigned char* __restrict__ mask,
      int K)
{
    extern __shared__ char smem[];
    const uint32_t sb = smem_u32(smem);
    const int tid = threadIdx.x;
    const int wid = tid >> 5;
    const int l   = tid & 31;
    const long m0 = (long)blockIdx.x * 128;
    const long n0 = (long)blockIdx.y * 128;
    const int  z  = blockIdx.z;

    Ah += (long)z * Az;  Al += (long)z * Az;
    Wh += (long)z * Wz + n0 * (long)K;
    Wl += (long)z * Wz + n0 * (long)K;
    Bv += (long)z * Bz + n0;

    if (tid < 128) ((float*)(smem + SBIAS))[tid] = Bv[tid];

    // Per-thread load slots: 8 cp.async of 16B per stage.
    // ops [0,512): A-hi, [512,1024): A-lo, same pattern for B.
    const int o0 = tid, o1 = tid + 256;
    const int r0 = o0 >> 2, c0 = o0 & 3;
    const int r1 = o1 >> 2, c1 = o1 & 3;

    const int NC = K >> 5;

    // ---- prologue: stage 0 ----
    {
        const int k0 = 0;
        const uint32_t st = sb;
        cp16(st + TA_H + r0 * ROWB + c0 * 16, Ah + (m0 + r0) * lda + k0 + c0 * 8);
        cp16(st + TA_H + r1 * ROWB + c1 * 16, Ah + (m0 + r1) * lda + k0 + c1 * 8);
        cp16(st + TA_L + r0 * ROWB + c0 * 16, Al + (m0 + r0) * lda + k0 + c0 * 8);
        cp16(st + TA_L + r1 * ROWB + c1 * 16, Al + (m0 + r1) * lda + k0 + c1 * 8);
        cp16(st + TB_H + r0 * ROWB + c0 * 16, Wh + (long)r0 * K + k0 + c0 * 8);
        cp16(st + TB_H + r1 * ROWB + c1 * 16, Wh + (long)r1 * K + k0 + c1 * 8);
        cp16(st + TB_L + r0 * ROWB + c0 * 16, Wl + (long)r0 * K + k0 + c0 * 8);
        cp16(st + TB_L + r1 * ROWB + c1 * 16, Wl + (long)r1 * K + k0 + c1 * 8);
        cp_commit();
    }

    const int warp_m = wid & 3;        // 0..3 -> m offset *32
    const int warp_n = wid >> 2;       // 0..1 -> n offset *64
    // ldmatrix lane address components
    const int a_r = l & 15;            // A row within m16
    const int a_k = (l >> 4) * 8;      // A k-half
    const int b_r = (l & 7) + ((l >> 4) << 3);   // B n row within n16
    const int b_k = ((l >> 3) & 1) * 8;          // B k-half

    float acc[2][8][4] = {};

    for (int i = 0; i < NC; i++) {
        if (i + 1 < NC) {
            const int k0 = (i + 1) << 5;
            const uint32_t st = sb + ((i + 1) & 1) * STG;
            cp16(st + TA_H + r0 * ROWB + c0 * 16, Ah + (m0 + r0) * lda + k0 + c0 * 8);
            cp16(st + TA_H + r1 * ROWB + c1 * 16, Ah + (m0 + r1) * lda + k0 + c1 * 8);
            cp16(st + TA_L + r0 * ROWB + c0 * 16, Al + (m0 + r0) * lda + k0 + c0 * 8);
            cp16(st + TA_L + r1 * ROWB + c1 * 16, Al + (m0 + r1) * lda + k0 + c1 * 8);
            cp16(st + TB_H + r0 * ROWB + c0 * 16, Wh + (long)r0 * K + k0 + c0 * 8);
            cp16(st + TB_H + r1 * ROWB + c1 * 16, Wh + (long)r1 * K + k0 + c1 * 8);
            cp16(st + TB_L + r0 * ROWB + c0 * 16, Wl + (long)r0 * K + k0 + c1 * 8 - c1 * 8 + c0 * 8);
            cp16(st + TB_L + r1 * ROWB + c1 * 16, Wl + (long)r1 * K + k0 + c1 * 8);
            cp_commit();
            cp_wait1();
        } else {
            cp_wait0();
        }
        __syncthreads();

        const uint32_t st = sb + (i & 1) * STG;
        #pragma unroll
        for (int ks = 0; ks < 32; ks += 16) {
            uint32_t ahf[2][4], alf[2][4];
            #pragma unroll
            for (int mt = 0; mt < 2; mt++) {
                const uint32_t arow = (warp_m * 32 + mt * 16 + a_r) * ROWB + (ks + a_k) * 2;
                ldsm4(ahf[mt], st + TA_H + arow);
                ldsm4(alf[mt], st + TA_L + arow);
            }
            #pragma unroll
            for (int g = 0; g < 4; g++) {
                uint32_t bhf[4], blf[4];
                const uint32_t brow = (warp_n * 64 + g * 16 + b_r) * ROWB + (ks + b_k) * 2;
                ldsm4(bhf, st + TB_H + brow);
                ldsm4(blf, st + TB_L + brow);
                #pragma unroll
                for (int mt = 0; mt < 2; mt++) {
                    #pragma unroll
                    for (int pr = 0; pr < 2; pr++) {
                        float* d = acc[mt][g * 2 + pr];
                        mma16816(d, ahf[mt], &bhf[pr * 2]);   // hi*hi
                        mma16816(d, ahf[mt], &blf[pr * 2]);   // hi*lo
                        mma16816(d, alf[mt], &bhf[pr * 2]);   // lo*hi
                    }
                }
            }
        }
        __syncthreads();
    }

    // ---- epilogue ----
    const float* bias_s = (const float*)(smem + SBIAS);

    #pragma unroll
    for (int mt = 0; mt < 2; mt++) {
        const long gr0 = m0 + warp_m * 32 + mt * 16 + (l >> 2);
        const long gr1 = gr0 + 8;
        #pragma unroll
        for (int nf = 0; nf < 8; nf++) {
            const int c = warp_n * 64 + nf * 8 + (l & 3) * 2;   // tile-local col
            const float b0 = bias_s[c], b1 = bias_s[c + 1];
            float v00 = acc[mt][nf][0] + b0, v01 = acc[mt][nf][1] + b1;
            float v10 = acc[mt][nf][2] + b0, v11 = acc[mt][nf][3] + b1;

            if (EPI == 1) {
                v00 = fmaxf(v00, 0.f); v01 = fmaxf(v01, 0.f);
                v10 = fmaxf(v10, 0.f); v11 = fmaxf(v11, 0.f);
            }

            if (EPI != 2) {
                __half h00 = __float2half_rn(v00), h01 = __float2half_rn(v01);
                __half h10 = __float2half_rn(v10), h11 = __float2half_rn(v11);
                __half l00 = __float2half_rn(v00 - __half2float(h00));
                __half l01 = __float2half_rn(v01 - __half2float(h01));
                __half l10 = __float2half_rn(v10 - __half2float(h10));
                __half l11 = __float2half_rn(v11 - __half2float(h11));
                __half* ch0 = Ch + (long)z * Cz + gr0 * ldc + n0 + c;
                __half* ch1 = Ch + (long)z * Cz + gr1 * ldc + n0 + c;
                __half* cl0 = Cl + (long)z * Cz + gr0 * ldc + n0 + c;
                __half* cl1 = Cl + (long)z * Cz + gr1 * ldc + n0 + c;
                *(__half2*)ch0 = __halves2half2(h00, h01);
                *(__half2*)ch1 = __halves2half2(h10, h11);
                *(__half2*)cl0 = __halves2half2(l00, l01);
                *(__half2*)cl1 = __halves2half2(l10, l11);
            } else {
                const int y = blockIdx.y;           // 0 = mu, 1 = var
                if (y == 1) {
                    v00 = 0.01f + 0.99f * softplusf(v00);
                    v01 = 0.01f + 0.99f * softplusf(v01);
                    v10 = 0.01f + 0.99f * softplusf(v10);
                    v11 = 0.01f + 0.99f * softplusf(v11);
                }
                const long f0 = gr0 * PD + z;
                const long f1 = gr1 * PD + z;
                const float nanv = __int_as_float(0x7FC00000);
                float m00 = v00, m01 = v01, m10 = v10, m11 = v11;
                if (mask[f0] != 0) { m00 = nanv; m01 = nanv; }
                if (mask[f1] != 0) { m10 = nanv; m11 = nanv; }
                float* ob = Fout + (long)y * ((long)NP * OUTD);
                float* p0 = ob + f0 * OUTD + c;
                float* p1 = ob + f1 * OUTD + c;
                p0[0] = m00; p0[1] = m01;
                p1[0] = m10; p1[1] = m11;
            }
        }
    }
}

extern "C" void kernel_launch(void* const* d_in, const int* in_sizes, int n_in,
                              void* d_out, int out_size)
{
    const float* x    = (const float*)d_in[0];
    const unsigned char* mask = (const unsigned char*)d_in[1];
    const float* W_in = (const float*)d_in[2];
    const float* b_in = (const float*)d_in[3];
    const float* W1   = (const float*)d_in[4];
    const float* b1   = (const float*)d_in[5];
    const float* W2   = (const float*)d_in[6];
    const float* b2   = (const float*)d_in[7];
    const float* W3   = (const float*)d_in[8];
    const float* b3   = (const float*)d_in[9];
    const float* Wout = (const float*)d_in[10];
    const float* bout = (const float*)d_in[11];
    float* out = (float*)d_out;

    __half *xh, *xl, *h0h, *h0l, *h1h, *h1l, *h2h, *h2l, *h3h, *h3l;
    __half *wih, *wil, *w1h, *w1l, *w2h, *w2l, *w3h, *w3l, *woh, *wol;
    cudaGetSymbolAddress((void**)&xh,  g_xh);  cudaGetSymbolAddress((void**)&xl,  g_xl);
    cudaGetSymbolAddress((void**)&h0h, g_h0h); cudaGetSymbolAddress((void**)&h0l, g_h0l);
    cudaGetSymbolAddress((void**)&h1h, g_h1h); cudaGetSymbolAddress((void**)&h1l, g_h1l);
    cudaGetSymbolAddress((void**)&h2h, g_h2h); cudaGetSymbolAddress((void**)&h2l, g_h2l);
    cudaGetSymbolAddress((void**)&h3h, g_h3h); cudaGetSymbolAddress((void**)&h3l, g_h3l);
    cudaGetSymbolAddress((void**)&wih, g_wih); cudaGetSymbolAddress((void**)&wil, g_wil);
    cudaGetSymbolAddress((void**)&w1h, g_w1h); cudaGetSymbolAddress((void**)&w1l, g_w1l);
    cudaGetSymbolAddress((void**)&w2h, g_w2h); cudaGetSymbolAddress((void**)&w2l, g_w2l);
    cudaGetSymbolAddress((void**)&w3h, g_w3h); cudaGetSymbolAddress((void**)&w3l, g_w3l);
    cudaGetSymbolAddress((void**)&woh, g_woh); cudaGetSymbolAddress((void**)&wol, g_wol);

    cudaFuncSetAttribute(hgemm<0>, cudaFuncAttributeMaxDynamicSharedMemorySize, SMEMT);
    cudaFuncSetAttribute(hgemm<1>, cudaFuncAttributeMaxDynamicSharedMemorySize, SMEMT);
    cudaFuncSetAttribute(hgemm<2>, cudaFuncAttributeMaxDynamicSharedMemorySize, SMEMT);

    // ---- fp32 -> fp16 hi/lo conversions ----
    cvt_hilo<<<2048, 256>>>(x,    xh,  xl,  (long)NP * IND / 4);
    cvt_hilo<<<512,  256>>>(W_in, wih, wil, (long)PD * HH0 * IND / 4);
    cvt_hilo<<<512,  256>>>(W1,   w1h, w1l, (long)HH1 * HH0 / 4);
    cvt_hilo<<<512,  256>>>(W2,   w2h, w2l, (long)HH2 * HH1 / 4);
    cvt_hilo<<<512,  256>>>(W3,   w3h, w3l, (long)HH3 * HH2 / 4);
    cvt_hilo<<<512,  256>>>(Wout, woh, wol, (long)PD * 2 * OUTD * HH3 / 4);

    // ---- Layer 0: per-p input projection (linear) ----
    hgemm<0><<<dim3(NPTS / 128, HH0 / 128, PD), 256, SMEMT>>>(
        xh, xl, (long)PD * IND, (long)IND,
        wih, wil, (long)HH0 * IND,
        b_in, (long)HH0,
        h0h, h0l, (long)PD * HH0, (long)HH0,
        nullptr, nullptr, IND);

    // ---- Layer 1: relu ----
    hgemm<1><<<dim3(NP / 128, HH1 / 128, 1), 256, SMEMT>>>(
        h0h, h0l, HH0, 0, w1h, w1l, 0, b1, 0,
        h1h, h1l, HH1, 0, nullptr, nullptr, HH0);

    // ---- Layer 2: relu ----
    hgemm<1><<<dim3(NP / 128, HH2 / 128, 1), 256, SMEMT>>>(
        h1h, h1l, HH1, 0, w2h, w2l, 0, b2, 0,
        h2h, h2l, HH2, 0, nullptr, nullptr, HH1);

    // ---- Layer 3: relu ----
    hgemm<1><<<dim3(NP / 128, HH3 / 128, 1), 256, SMEMT>>>(
        h2h, h2l, HH2, 0, w3h, w3l, 0, b3, 0,
        h3h, h3l, HH3, 0, nullptr, nullptr, HH2);

    // ---- Output head: y=0 mu, y=1 var(softplus), mask -> NaN ----
    hgemm<2><<<dim3(NPTS / 128, 2, PD), 256, SMEMT>>>(
        h3h, h3l, (long)PD * HH3, (long)HH3,
        woh, wol, (long)(2 * OUTD) * HH3,
        bout, (long)(2 * OUTD),
        nullptr, nullptr, 0, 0,
        out, mask, HH3);
}